// round 2
// baseline (speedup 1.0000x reference)
#include <cuda_runtime.h>
#include <cuda_bf16.h>

#define SQ    256
#define BATCH 16
#define EMB   512
#define HID   256
#define HMD   128
#define G4    1024            // 4*HID
#define NROWS (SQ*BATCH)      // 4096
#define INW   512             // input width both layers (E = 2H = 512)
#define NSC   (BATCH*SQ*SQ)   // 1,048,576 scores

// ---------------- scratch (device globals; no allocations allowed) ----------
__device__ float g_xa[NROWS * EMB];                 // 8 MB
__device__ float g_xb[NROWS * EMB];                 // 8 MB
__device__ float g_xproj[2 * SQ * G4 * BATCH];      // 32 MB : [dir][t][gate(1024)][b]
__device__ float g_hbuf[2][2][BATCH * HID];         // [pingpong][dir][b*256+k]
__device__ float g_p[BATCH * SQ * HMD];             // 2 MB
__device__ float g_cq[BATCH * SQ * HMD];            // 2 MB
__device__ unsigned g_bar_count;
__device__ unsigned g_bar_phase;

// ---------------- math helpers ----------------------------------------------
__device__ __forceinline__ float ftanh(float x) {
    x = fminf(fmaxf(x, -15.f), 15.f);
    float e = __expf(2.f * x);
    return 1.f - __fdividef(2.f, e + 1.f);
}
__device__ __forceinline__ float fsig(float x) {
    x = fminf(fmaxf(x, -30.f), 30.f);
    return __fdividef(1.f, 1.f + __expf(-x));
}

// ---------------- grid barrier (all 128 blocks resident) --------------------
__device__ __forceinline__ void grid_barrier(unsigned nb) {
    __syncthreads();
    if (threadIdx.x == 0) {
        unsigned ph = *((volatile unsigned*)&g_bar_phase);
        __threadfence();
        unsigned old = atomicAdd(&g_bar_count, 1u);
        if (old == nb - 1u) {
            g_bar_count = 0u;
            __threadfence();
            *((volatile unsigned*)&g_bar_phase) = ph + 1u;
        } else {
            while (*((volatile unsigned*)&g_bar_phase) == ph) { }
        }
        __threadfence();
    }
    __syncthreads();
}

// ---------------- 1) embedding gather ---------------------------------------
__global__ __launch_bounds__(128) void embed_kernel(const int* __restrict__ concepts,
                                                    const float* __restrict__ emb) {
    int row = blockIdx.x;                       // s*16 + b
    int tok = concepts[row];
    const float4* src = (const float4*)(emb + (size_t)tok * EMB);
    float4* dst = (float4*)(g_xa + (size_t)row * EMB);
    dst[threadIdx.x] = src[threadIdx.x];        // 128 * float4 = 512 floats
}

// ---------------- 2) input projection GEMM: [4096,512] x [2048,512]^T -------
// out: g_xproj[((dir*256 + s)*1024 + g)*16 + b]   (b fastest for recurrence)
__global__ __launch_bounds__(256) void inproj_kernel(int layer,
                                                     const float* __restrict__ W,
                                                     const float* __restrict__ bias) {
    const float* __restrict__ A = layer ? g_xb : g_xa;
    __shared__ float As[16][68];
    __shared__ float Bs[16][68];
    int m0 = blockIdx.y << 6;
    int n0 = blockIdx.x << 6;
    int tid = threadIdx.x;
    int tm = tid >> 4, tn = tid & 15;
    int lr = tid >> 2, lc = (tid & 3) << 2;

    float acc[4][4];
#pragma unroll
    for (int i = 0; i < 4; i++)
#pragma unroll
        for (int j = 0; j < 4; j++) acc[i][j] = 0.f;

    for (int k0 = 0; k0 < INW; k0 += 16) {
        float4 av = *(const float4*)&A[(size_t)(m0 + lr) * INW + k0 + lc];
        float4 bv = *(const float4*)&W[(size_t)(n0 + lr) * INW + k0 + lc];
        As[lc + 0][lr] = av.x; As[lc + 1][lr] = av.y; As[lc + 2][lr] = av.z; As[lc + 3][lr] = av.w;
        Bs[lc + 0][lr] = bv.x; Bs[lc + 1][lr] = bv.y; Bs[lc + 2][lr] = bv.z; Bs[lc + 3][lr] = bv.w;
        __syncthreads();
#pragma unroll
        for (int kk = 0; kk < 16; kk++) {
            float4 a4 = *(const float4*)&As[kk][tm << 2];
            float4 b4 = *(const float4*)&Bs[kk][tn << 2];
            float aa[4] = {a4.x, a4.y, a4.z, a4.w};
            float bb[4] = {b4.x, b4.y, b4.z, b4.w};
#pragma unroll
            for (int i = 0; i < 4; i++)
#pragma unroll
                for (int j = 0; j < 4; j++) acc[i][j] += aa[i] * bb[j];
        }
        __syncthreads();
    }
#pragma unroll
    for (int i = 0; i < 4; i++) {
        int m = m0 + (tm << 2) + i;
        int s = m >> 4, b = m & 15;
#pragma unroll
        for (int j = 0; j < 4; j++) {
            int n = n0 + (tn << 2) + j;
            int d = n >> 10, g = n & 1023;
            g_xproj[(size_t)((((d << 8) | s) << 10) | g) * BATCH + b] = acc[i][j] + bias[n];
        }
    }
}

// ---------------- 3) LSTM recurrence (persistent, 128 blocks, 256 thr) ------
__global__ __launch_bounds__(256) void lstm_rec_kernel(int layer,
                                                       const float* __restrict__ whh) {
    float* __restrict__ xout = layer ? g_xa : g_xb;
    int dir = blockIdx.x >> 6;
    int gb  = blockIdx.x & 63;
    int j0  = gb << 2;                 // 4 hidden units per block
    int tid = threadIdx.x;

    __shared__ float w_s[16][260];
    __shared__ float h_s[16][260];
    __shared__ float gate_s[16][17];

#pragma unroll
    for (int r = 0; r < 16; r++) {     // row r = gate q (r>>2), unit u (r&3)
        int q = r >> 2, u = r & 3;
        w_s[r][tid] = whh[(size_t)((dir << 10) + (q << 8) + j0 + u) * HID + tid];
    }
    if (tid < 64) {
        int b = tid & 15, u = tid >> 4;
        __stcg(&g_hbuf[0][dir][(b << 8) + j0 + u], 0.f);
    }
    float c_reg = 0.f;
    int b_ = tid & 15, r_ = tid >> 4;
    int q_ = r_ >> 2, u_ = r_ & 3;
    int off0 = (dir << 22) + ((q_ << 8) + j0 + u_) * BATCH + b_;

    grid_barrier(gridDim.x);

    for (int p = 0; p < SQ; p++) {
        int t = dir ? (SQ - 1 - p) : p;
        const float* hsrc = g_hbuf[p & 1][dir];
#pragma unroll
        for (int i = 0; i < 16; i++)
            h_s[i][tid] = __ldcg(&hsrc[tid + (i << 8)]);
        float acc = __ldg(&g_xproj[off0 + (t << 14)]);
        __syncthreads();
        const float* wrow = &w_s[r_][0];
        const float* hrow = &h_s[b_][0];
#pragma unroll 8
        for (int k = 0; k < HID; k += 4) {
            float4 wv = *(const float4*)&wrow[k];
            float4 hv = *(const float4*)&hrow[k];
            acc += wv.x * hv.x;
            acc += wv.y * hv.y;
            acc += wv.z * hv.z;
            acc += wv.w * hv.w;
        }
        gate_s[r_][b_] = acc;
        __syncthreads();
        if (tid < 64) {
            int b = tid & 15, u = tid >> 4;
            float gi = gate_s[u][b];
            float gf = gate_s[4 + u][b];
            float gg = gate_s[8 + u][b];
            float go = gate_s[12 + u][b];
            c_reg = fsig(gf) * c_reg + fsig(gi) * ftanh(gg);
            float h = fsig(go) * ftanh(c_reg);
            __stcg(&g_hbuf[(p + 1) & 1][dir][(b << 8) + j0 + u], h);
            xout[(size_t)((t * BATCH + b) << 9) + (dir << 8) + j0 + u] = h;
        }
        grid_barrier(gridDim.x);
    }
}

// ---------------- 4) attention projections ----------------------------------
// n0 in {0,64} -> Ua -> g_p[(b*256+s)*128+n] ; n0 in {128,192} -> Wa -> g_cq
__global__ __launch_bounds__(256) void attnproj_kernel(const float* __restrict__ Ua,
                                                       const float* __restrict__ Wa) {
    const float* __restrict__ A = g_xa;   // layer-1 output [s][b][512]
    __shared__ float As[16][68];
    __shared__ float Bs[16][68];
    int m0 = blockIdx.y << 6;
    int n0 = blockIdx.x << 6;
    const float* Wsel = (n0 < 128) ? Ua : Wa;
    int nbase = (n0 < 128) ? n0 : (n0 - 128);
    float* out = (n0 < 128) ? g_p : g_cq;

    int tid = threadIdx.x;
    int tm = tid >> 4, tn = tid & 15;
    int lr = tid >> 2, lc = (tid & 3) << 2;

    float acc[4][4];
#pragma unroll
    for (int i = 0; i < 4; i++)
#pragma unroll
        for (int j = 0; j < 4; j++) acc[i][j] = 0.f;

    for (int k0 = 0; k0 < INW; k0 += 16) {
        float4 av = *(const float4*)&A[(size_t)(m0 + lr) * INW + k0 + lc];
        float4 bv = *(const float4*)&Wsel[(size_t)(nbase + lr) * INW + k0 + lc];
        As[lc + 0][lr] = av.x; As[lc + 1][lr] = av.y; As[lc + 2][lr] = av.z; As[lc + 3][lr] = av.w;
        Bs[lc + 0][lr] = bv.x; Bs[lc + 1][lr] = bv.y; Bs[lc + 2][lr] = bv.z; Bs[lc + 3][lr] = bv.w;
        __syncthreads();
#pragma unroll
        for (int kk = 0; kk < 16; kk++) {
            float4 a4 = *(const float4*)&As[kk][tm << 2];
            float4 b4 = *(const float4*)&Bs[kk][tn << 2];
            float aa[4] = {a4.x, a4.y, a4.z, a4.w};
            float bb[4] = {b4.x, b4.y, b4.z, b4.w};
#pragma unroll
            for (int i = 0; i < 4; i++)
#pragma unroll
                for (int j = 0; j < 4; j++) acc[i][j] += aa[i] * bb[j];
        }
        __syncthreads();
    }
#pragma unroll
    for (int i = 0; i < 4; i++) {
        int m = m0 + (tm << 2) + i;
        int s = m >> 4, b = m & 15;
#pragma unroll
        for (int j = 0; j < 4; j++) {
            int nl = nbase + (tn << 2) + j;
            out[(size_t)(((b << 8) + s) << 7) + nl] = acc[i][j];
        }
    }
}

// ---------------- 5) pairwise scores + predictions --------------------------
// scores[b,i,j] = sum_h va[h]*tanh(p[b,i,h]+c[b,j,h]);  pred = (score >= 0)
__global__ __launch_bounds__(256) void scores_kernel(const float* __restrict__ va,
                                                     float* __restrict__ out,
                                                     int write_pred) {
    __shared__ float ps[32][132];
    __shared__ float cs[32][132];
    __shared__ float va_s[HMD];
    int b  = blockIdx.z;
    int i0 = blockIdx.y << 5, j0 = blockIdx.x << 5;
    int tid = threadIdx.x;
    if (tid < HMD) va_s[tid] = va[tid];
#pragma unroll
    for (int i = 0; i < 4; i++) {
        int f4 = tid + (i << 8);                 // 1024 float4s total
        int row = f4 >> 5;
        int col = (f4 & 31) << 2;
        *(float4*)&ps[row][col] =
            *(const float4*)&g_p[(size_t)(((b << 8) + i0 + row) << 7) + col];
        *(float4*)&cs[row][col] =
            *(const float4*)&g_cq[(size_t)(((b << 8) + j0 + row) << 7) + col];
    }
    __syncthreads();

    int tj = tid & 15, ti = tid >> 4;
    int ia = ti << 1, ja = tj << 1;
    float s00 = 0.f, s01 = 0.f, s10 = 0.f, s11 = 0.f;
#pragma unroll 4
    for (int h = 0; h < HMD; h++) {
        float v  = va_s[h];
        float pa = ps[ia][h],     pb = ps[ia + 1][h];
        float ca = cs[ja][h],     cb = cs[ja + 1][h];
        s00 += v * ftanh(pa + ca);
        s01 += v * ftanh(pa + cb);
        s10 += v * ftanh(pb + ca);
        s11 += v * ftanh(pb + cb);
    }
    int gi = i0 + ia, gj = j0 + ja;
    size_t base = ((size_t)b << 16) + ((size_t)gi << 8) + gj;
    out[base]           = s00;
    out[base + 1]       = s01;
    out[base + 256]     = s10;
    out[base + 257]     = s11;
    if (write_pred) {
        float* po = out + NSC;
        po[base]       = (s00 >= 0.f) ? 1.f : 0.f;
        po[base + 1]   = (s01 >= 0.f) ? 1.f : 0.f;
        po[base + 256] = (s10 >= 0.f) ? 1.f : 0.f;
        po[base + 257] = (s11 >= 0.f) ? 1.f : 0.f;
    }
}

// ---------------- launch -----------------------------------------------------
extern "C" void kernel_launch(void* const* d_in, const int* in_sizes, int n_in,
                              void* d_out, int out_size) {
    const int*   concepts = (const int*)d_in[0];
    // d_in[1] = concepts_lengths (all full-length; unused)
    const float* emb  = (const float*)d_in[2];
    const float* w_ih = (const float*)d_in[3];
    const float* w_hh = (const float*)d_in[4];
    const float* bias = (const float*)d_in[5];
    const float* Ua   = (const float*)d_in[6];
    const float* Wa   = (const float*)d_in[7];
    const float* va   = (const float*)d_in[8];
    float* out = (float*)d_out;

    embed_kernel<<<NROWS, 128>>>(concepts, emb);

    // layer 0
    inproj_kernel<<<dim3(32, 64), 256>>>(0, w_ih, bias);
    lstm_rec_kernel<<<128, 256>>>(0, w_hh);
    // layer 1
    inproj_kernel<<<dim3(32, 64), 256>>>(1, w_ih + 2 * G4 * EMB, bias + 2 * G4);
    lstm_rec_kernel<<<128, 256>>>(1, w_hh + 2 * G4 * HID);

    attnproj_kernel<<<dim3(4, 64), 256>>>(Ua, Wa);

    int write_pred = (out_size >= 2 * NSC) ? 1 : 0;
    scores_kernel<<<dim3(8, 8, BATCH), 256>>>(va, out, write_pred);
}

// round 3
// speedup vs baseline: 1.0687x; 1.0687x over previous
#include <cuda_runtime.h>
#include <cuda_bf16.h>

#define SQ    256
#define BATCH 16
#define EMB   512
#define HID   256
#define HMD   128
#define G4    1024            // 4*HID
#define NROWS (SQ*BATCH)      // 4096
#define INW   512             // input width both layers (E = 2H = 512)
#define NSC   (BATCH*SQ*SQ)   // 1,048,576 scores

// ---------------- scratch (device globals; no allocations allowed) ----------
__device__ float g_xa[NROWS * EMB];                 // 8 MB
__device__ float g_xb[NROWS * EMB];                 // 8 MB
__device__ float g_xproj[2 * SQ * G4 * BATCH];      // 32 MB : [dir][t][gate(1024)][b]
__device__ float g_hbuf[2][2][BATCH * HID];         // [pingpong][dir][b*256+k]
__device__ float g_p[BATCH * SQ * HMD];             // 2 MB
__device__ float g_cq[BATCH * SQ * HMD];            // 2 MB
__device__ unsigned g_arrive[2][64];                // per-dir distributed barrier flags

// ---------------- f32x2 packed math ------------------------------------------
__device__ __forceinline__ unsigned long long ffma2(unsigned long long a,
                                                    unsigned long long b,
                                                    unsigned long long c) {
    unsigned long long d;
    asm("fma.rn.f32x2 %0, %1, %2, %3;" : "=l"(d) : "l"(a), "l"(b), "l"(c));
    return d;
}
__device__ __forceinline__ unsigned long long pack2(float x, float y) {
    unsigned long long d;
    asm("mov.b64 %0, {%1, %2};" : "=l"(d) : "f"(x), "f"(y));
    return d;
}
__device__ __forceinline__ float2 unpack2(unsigned long long v) {
    float2 r;
    asm("mov.b64 {%0, %1}, %2;" : "=f"(r.x), "=f"(r.y) : "l"(v));
    return r;
}

// ---------------- scalar math helpers ----------------------------------------
__device__ __forceinline__ float ftanh(float x) {
    x = fminf(fmaxf(x, -15.f), 15.f);
    float e = __expf(2.f * x);
    return 1.f - __fdividef(2.f, e + 1.f);
}
__device__ __forceinline__ float fsig(float x) {
    x = fminf(fmaxf(x, -30.f), 30.f);
    return __fdividef(1.f, 1.f + __expf(-x));
}

// ---------------- 1) embedding gather (+ barrier flag reset) -----------------
__global__ __launch_bounds__(128) void embed_kernel(const int* __restrict__ concepts,
                                                    const float* __restrict__ emb) {
    if (blockIdx.x == 0 && threadIdx.x < 128)
        __stcg(&g_arrive[threadIdx.x >> 6][threadIdx.x & 63], 0u);
    int row = blockIdx.x;                       // s*16 + b
    int tok = concepts[row];
    const float4* src = (const float4*)(emb + (size_t)tok * EMB);
    float4* dst = (float4*)(g_xa + (size_t)row * EMB);
    dst[threadIdx.x] = src[threadIdx.x];        // 128 * float4 = 512 floats
}

// ---------------- 2) input projection GEMM: [4096,512] x [2048,512]^T -------
// out: g_xproj[((dir*256 + s)*1024 + g)*16 + b]   (b fastest for recurrence)
__global__ __launch_bounds__(256) void inproj_kernel(int layer,
                                                     const float* __restrict__ W,
                                                     const float* __restrict__ bias) {
    const float* __restrict__ A = layer ? g_xb : g_xa;
    __shared__ __align__(16) float As[16][68];
    __shared__ __align__(16) float Bs[16][68];
    int m0 = blockIdx.y << 6;
    int n0 = blockIdx.x << 6;
    int tid = threadIdx.x;
    int tm = tid >> 4, tn = tid & 15;
    int lr = tid >> 2, lc = (tid & 3) << 2;

    unsigned long long accp[4][2];
#pragma unroll
    for (int i = 0; i < 4; i++) { accp[i][0] = 0ull; accp[i][1] = 0ull; }

    for (int k0 = 0; k0 < INW; k0 += 16) {
        float4 av = *(const float4*)&A[(size_t)(m0 + lr) * INW + k0 + lc];
        float4 bv = *(const float4*)&W[(size_t)(n0 + lr) * INW + k0 + lc];
        As[lc + 0][lr] = av.x; As[lc + 1][lr] = av.y; As[lc + 2][lr] = av.z; As[lc + 3][lr] = av.w;
        Bs[lc + 0][lr] = bv.x; Bs[lc + 1][lr] = bv.y; Bs[lc + 2][lr] = bv.z; Bs[lc + 3][lr] = bv.w;
        __syncthreads();
#pragma unroll
        for (int kk = 0; kk < 16; kk++) {
            float4 a4 = *(const float4*)&As[kk][tm << 2];
            ulonglong2 b2 = *(const ulonglong2*)&Bs[kk][tn << 2];
            unsigned long long ad0 = pack2(a4.x, a4.x);
            unsigned long long ad1 = pack2(a4.y, a4.y);
            unsigned long long ad2 = pack2(a4.z, a4.z);
            unsigned long long ad3 = pack2(a4.w, a4.w);
            accp[0][0] = ffma2(ad0, b2.x, accp[0][0]);
            accp[0][1] = ffma2(ad0, b2.y, accp[0][1]);
            accp[1][0] = ffma2(ad1, b2.x, accp[1][0]);
            accp[1][1] = ffma2(ad1, b2.y, accp[1][1]);
            accp[2][0] = ffma2(ad2, b2.x, accp[2][0]);
            accp[2][1] = ffma2(ad2, b2.y, accp[2][1]);
            accp[3][0] = ffma2(ad3, b2.x, accp[3][0]);
            accp[3][1] = ffma2(ad3, b2.y, accp[3][1]);
        }
        __syncthreads();
    }
#pragma unroll
    for (int i = 0; i < 4; i++) {
        int m = m0 + (tm << 2) + i;
        int s = m >> 4, b = m & 15;
        float2 u0 = unpack2(accp[i][0]);
        float2 u1 = unpack2(accp[i][1]);
        float vals[4] = {u0.x, u0.y, u1.x, u1.y};
#pragma unroll
        for (int j = 0; j < 4; j++) {
            int n = n0 + (tn << 2) + j;
            int d = n >> 10, g = n & 1023;
            g_xproj[(size_t)((((d << 8) | s) << 10) | g) * BATCH + b] = vals[j] + bias[n];
        }
    }
}

// ---------------- 3) LSTM recurrence (persistent, 128 blocks, 256 thr) ------
// 64 blocks per direction, per-dir distributed flag barrier (no atomics).
__global__ __launch_bounds__(256) void lstm_rec_kernel(int layer,
                                                       const float* __restrict__ whh) {
    float* __restrict__ xout = layer ? g_xa : g_xb;
    int dir = blockIdx.x >> 6;
    int gb  = blockIdx.x & 63;
    int j0  = gb << 2;                 // 4 hidden units per block
    int tid = threadIdx.x;

    __shared__ __align__(16) float w_s[16][260];
    __shared__ __align__(16) float h_s[16][260];
    __shared__ float gate_s[16][17];

#pragma unroll
    for (int r = 0; r < 16; r++) {     // row r = gate q (r>>2), unit u (r&3)
        int q = r >> 2, u = r & 3;
        w_s[r][tid] = whh[(size_t)((dir << 10) + (q << 8) + j0 + u) * HID + tid];
    }
    if (tid < 64) {
        int b = tid & 15, u = tid >> 4;
        __stcg(&g_hbuf[0][dir][(b << 8) + j0 + u], 0.f);
    }
    float c_reg = 0.f;
    int b_ = tid & 15, r_ = tid >> 4;
    int q_ = r_ >> 2, u_ = r_ & 3;
    int off0 = (dir << 22) + ((q_ << 8) + j0 + u_) * BATCH + b_;

    unsigned base = (unsigned)layer * 300u;
    // ---- distributed barrier: signal own flag, poll all 64 of this dir ----
#define DIR_BARRIER(TARGET)                                                     \
    do {                                                                        \
        unsigned _tg = (TARGET);                                                \
        __syncthreads();                                                        \
        if (tid == 0) { __threadfence(); __stcg(&g_arrive[dir][gb], _tg); }     \
        for (;;) {                                                              \
            int ok = (tid < 64) ? (__ldcg(&g_arrive[dir][tid]) >= _tg) : 1;     \
            if (__syncthreads_count(ok) == 256) break;                          \
        }                                                                       \
        __threadfence();                                                        \
    } while (0)

    DIR_BARRIER(base + 1u);            // h(0) visible everywhere

    for (int p = 0; p < SQ; p++) {
        int t = dir ? (SQ - 1 - p) : p;
        const float* hsrc = g_hbuf[p & 1][dir];
#pragma unroll
        for (int i = 0; i < 16; i++)
            h_s[i][tid] = __ldcg(&hsrc[tid + (i << 8)]);
        float acc = __ldg(&g_xproj[off0 + (t << 14)]);
        __syncthreads();
        const float* wrow = &w_s[r_][0];
        const float* hrow = &h_s[b_][0];
        unsigned long long a0 = 0ull, a1 = 0ull;
#pragma unroll 8
        for (int k = 0; k < HID; k += 8) {
            ulonglong2 wv0 = *(const ulonglong2*)&wrow[k];
            ulonglong2 hv0 = *(const ulonglong2*)&hrow[k];
            a0 = ffma2(wv0.x, hv0.x, a0);
            a1 = ffma2(wv0.y, hv0.y, a1);
            ulonglong2 wv1 = *(const ulonglong2*)&wrow[k + 4];
            ulonglong2 hv1 = *(const ulonglong2*)&hrow[k + 4];
            a0 = ffma2(wv1.x, hv1.x, a0);
            a1 = ffma2(wv1.y, hv1.y, a1);
        }
        float2 f0 = unpack2(a0), f1 = unpack2(a1);
        acc += (f0.x + f0.y) + (f1.x + f1.y);
        gate_s[r_][b_] = acc;
        __syncthreads();
        if (tid < 64) {
            int b = tid & 15, u = tid >> 4;
            float gi = gate_s[u][b];
            float gf = gate_s[4 + u][b];
            float gg = gate_s[8 + u][b];
            float go = gate_s[12 + u][b];
            c_reg = fsig(gf) * c_reg + fsig(gi) * ftanh(gg);
            float h = fsig(go) * ftanh(c_reg);
            __stcg(&g_hbuf[(p + 1) & 1][dir][(b << 8) + j0 + u], h);
            xout[(size_t)((t * BATCH + b) << 9) + (dir << 8) + j0 + u] = h;
        }
        DIR_BARRIER(base + 2u + (unsigned)p);
    }
#undef DIR_BARRIER
}

// ---------------- 4) attention projections ----------------------------------
// n0 in {0,64} -> Ua -> g_p[(b*256+s)*128+n] ; n0 in {128,192} -> Wa -> g_cq
__global__ __launch_bounds__(256) void attnproj_kernel(const float* __restrict__ Ua,
                                                       const float* __restrict__ Wa) {
    const float* __restrict__ A = g_xa;   // layer-1 output [s][b][512]
    __shared__ __align__(16) float As[16][68];
    __shared__ __align__(16) float Bs[16][68];
    int m0 = blockIdx.y << 6;
    int n0 = blockIdx.x << 6;
    const float* Wsel = (n0 < 128) ? Ua : Wa;
    int nbase = (n0 < 128) ? n0 : (n0 - 128);
    float* out = (n0 < 128) ? g_p : g_cq;

    int tid = threadIdx.x;
    int tm = tid >> 4, tn = tid & 15;
    int lr = tid >> 2, lc = (tid & 3) << 2;

    unsigned long long accp[4][2];
#pragma unroll
    for (int i = 0; i < 4; i++) { accp[i][0] = 0ull; accp[i][1] = 0ull; }

    for (int k0 = 0; k0 < INW; k0 += 16) {
        float4 av = *(const float4*)&A[(size_t)(m0 + lr) * INW + k0 + lc];
        float4 bv = *(const float4*)&Wsel[(size_t)(nbase + lr) * INW + k0 + lc];
        As[lc + 0][lr] = av.x; As[lc + 1][lr] = av.y; As[lc + 2][lr] = av.z; As[lc + 3][lr] = av.w;
        Bs[lc + 0][lr] = bv.x; Bs[lc + 1][lr] = bv.y; Bs[lc + 2][lr] = bv.z; Bs[lc + 3][lr] = bv.w;
        __syncthreads();
#pragma unroll
        for (int kk = 0; kk < 16; kk++) {
            float4 a4 = *(const float4*)&As[kk][tm << 2];
            ulonglong2 b2 = *(const ulonglong2*)&Bs[kk][tn << 2];
            unsigned long long ad0 = pack2(a4.x, a4.x);
            unsigned long long ad1 = pack2(a4.y, a4.y);
            unsigned long long ad2 = pack2(a4.z, a4.z);
            unsigned long long ad3 = pack2(a4.w, a4.w);
            accp[0][0] = ffma2(ad0, b2.x, accp[0][0]);
            accp[0][1] = ffma2(ad0, b2.y, accp[0][1]);
            accp[1][0] = ffma2(ad1, b2.x, accp[1][0]);
            accp[1][1] = ffma2(ad1, b2.y, accp[1][1]);
            accp[2][0] = ffma2(ad2, b2.x, accp[2][0]);
            accp[2][1] = ffma2(ad2, b2.y, accp[2][1]);
            accp[3][0] = ffma2(ad3, b2.x, accp[3][0]);
            accp[3][1] = ffma2(ad3, b2.y, accp[3][1]);
        }
        __syncthreads();
    }
#pragma unroll
    for (int i = 0; i < 4; i++) {
        int m = m0 + (tm << 2) + i;
        int s = m >> 4, b = m & 15;
        float2 u0 = unpack2(accp[i][0]);
        float2 u1 = unpack2(accp[i][1]);
        float vals[4] = {u0.x, u0.y, u1.x, u1.y};
#pragma unroll
        for (int j = 0; j < 4; j++) {
            int nl = nbase + (tn << 2) + j;
            out[(size_t)(((b << 8) + s) << 7) + nl] = vals[j];
        }
    }
}

// ---------------- 5) pairwise scores + predictions --------------------------
// scores[b,i,j] = sum_h va[h]*tanh(p[b,i,h]+c[b,j,h]);  pred = (score >= 0)
__global__ __launch_bounds__(256) void scores_kernel(const float* __restrict__ va,
                                                     float* __restrict__ out,
                                                     int write_pred) {
    __shared__ __align__(16) float ps[32][132];
    __shared__ __align__(16) float cs[32][132];
    __shared__ float va_s[HMD];
    int b  = blockIdx.z;
    int i0 = blockIdx.y << 5, j0 = blockIdx.x << 5;
    int tid = threadIdx.x;
    if (tid < HMD) va_s[tid] = va[tid];
#pragma unroll
    for (int i = 0; i < 4; i++) {
        int f4 = tid + (i << 8);                 // 1024 float4s total
        int row = f4 >> 5;
        int col = (f4 & 31) << 2;
        *(float4*)&ps[row][col] =
            *(const float4*)&g_p[(size_t)(((b << 8) + i0 + row) << 7) + col];
        *(float4*)&cs[row][col] =
            *(const float4*)&g_cq[(size_t)(((b << 8) + j0 + row) << 7) + col];
    }
    __syncthreads();

    int tj = tid & 15, ti = tid >> 4;
    int ia = ti << 1, ja = tj << 1;
    float s00 = 0.f, s01 = 0.f, s10 = 0.f, s11 = 0.f;
#pragma unroll 4
    for (int h = 0; h < HMD; h++) {
        float v  = va_s[h];
        float pa = ps[ia][h],     pb = ps[ia + 1][h];
        float ca = cs[ja][h],     cb = cs[ja + 1][h];
        s00 += v * ftanh(pa + ca);
        s01 += v * ftanh(pa + cb);
        s10 += v * ftanh(pb + ca);
        s11 += v * ftanh(pb + cb);
    }
    int gi = i0 + ia, gj = j0 + ja;
    size_t base = ((size_t)b << 16) + ((size_t)gi << 8) + gj;
    out[base]           = s00;
    out[base + 1]       = s01;
    out[base + 256]     = s10;
    out[base + 257]     = s11;
    if (write_pred) {
        float* po = out + NSC;
        po[base]       = (s00 >= 0.f) ? 1.f : 0.f;
        po[base + 1]   = (s01 >= 0.f) ? 1.f : 0.f;
        po[base + 256] = (s10 >= 0.f) ? 1.f : 0.f;
        po[base + 257] = (s11 >= 0.f) ? 1.f : 0.f;
    }
}

// ---------------- launch -----------------------------------------------------
extern "C" void kernel_launch(void* const* d_in, const int* in_sizes, int n_in,
                              void* d_out, int out_size) {
    const int*   concepts = (const int*)d_in[0];
    // d_in[1] = concepts_lengths (all full-length; unused)
    const float* emb  = (const float*)d_in[2];
    const float* w_ih = (const float*)d_in[3];
    const float* w_hh = (const float*)d_in[4];
    const float* bias = (const float*)d_in[5];
    const float* Ua   = (const float*)d_in[6];
    const float* Wa   = (const float*)d_in[7];
    const float* va   = (const float*)d_in[8];
    float* out = (float*)d_out;

    embed_kernel<<<NROWS, 128>>>(concepts, emb);

    // layer 0
    inproj_kernel<<<dim3(32, 64), 256>>>(0, w_ih, bias);
    lstm_rec_kernel<<<128, 256>>>(0, w_hh);
    // layer 1
    inproj_kernel<<<dim3(32, 64), 256>>>(1, w_ih + 2 * G4 * EMB, bias + 2 * G4);
    lstm_rec_kernel<<<128, 256>>>(1, w_hh + 2 * G4 * HID);

    attnproj_kernel<<<dim3(4, 64), 256>>>(Ua, Wa);

    int write_pred = (out_size >= 2 * NSC) ? 1 : 0;
    scores_kernel<<<dim3(8, 8, BATCH), 256>>>(va, out, write_pred);
}